// round 17
// baseline (speedup 1.0000x reference)
#include <cuda_runtime.h>
#include <cuda_bf16.h>
#include <cstdint>

#define A_N 100000
#define B_N 200000
#define M_N 50000
#define H_N 128
#define NMOL_N 4000
#define MAXNB 8
#define FA 35
#define FB 40

// Scratch (device globals — no allocations allowed)
__device__ __align__(128) __nv_bfloat16 g_tr[(size_t)M_N * H_N];
__device__ __align__(128) __nv_bfloat16 g_gm0[(size_t)B_N * H_N];
__device__ __align__(128) __nv_bfloat16 g_gm1[(size_t)B_N * H_N];
__device__ __align__(128) float g_binput[(size_t)B_N * H_N];  // fp32 accuracy anchor
__device__ __align__(128) float g_ah[(size_t)A_N * H_N];
// W_h^T bf16 hi/lo split, padded [n][136] (272B stride) — "col" operand
#define BST 136
__device__ __align__(128) __nv_bfloat16 g_whT_h[H_N * BST];
__device__ __align__(128) __nv_bfloat16 g_whT_l[H_N * BST];

// ---- helpers --------------------------------------------------------------
__device__ __forceinline__ uint2 to_bf4(float4 o) {
    __nv_bfloat162 lo = __float22bfloat162_rn(make_float2(o.x, o.y));
    __nv_bfloat162 hi = __float22bfloat162_rn(make_float2(o.z, o.w));
    uint2 r;
    r.x = *(unsigned*)&lo;
    r.y = *(unsigned*)&hi;
    return r;
}
__device__ __forceinline__ unsigned bf2(float a, float b) {
    __nv_bfloat162 h = __floats2bfloat162_rn(a, b);
    return *(unsigned*)&h;
}
__device__ __forceinline__ uint32_t smem_u32(const void* p) {
    uint32_t a;
    asm("{ .reg .u64 t; cvta.to.shared.u64 t, %1; cvt.u32.u64 %0, t; }" : "=r"(a) : "l"(p));
    return a;
}
__device__ __forceinline__ void ldsm_x4(uint32_t addr, uint32_t& r0, uint32_t& r1,
                                        uint32_t& r2, uint32_t& r3) {
    asm volatile("ldmatrix.sync.aligned.m8n8.x4.shared.b16 {%0,%1,%2,%3}, [%4];"
                 : "=r"(r0), "=r"(r1), "=r"(r2), "=r"(r3) : "r"(addr));
}
__device__ __forceinline__ void mma16816(float c[4], uint32_t a0, uint32_t a1,
                                         uint32_t a2, uint32_t a3,
                                         uint32_t b0, uint32_t b1) {
    asm volatile(
        "mma.sync.aligned.m16n8k16.row.col.f32.bf16.bf16.f32 "
        "{%0,%1,%2,%3}, {%4,%5,%6,%7}, {%8,%9}, {%0,%1,%2,%3};"
        : "+f"(c[0]), "+f"(c[1]), "+f"(c[2]), "+f"(c[3])
        : "r"(a0), "r"(a1), "r"(a2), "r"(a3), "r"(b0), "r"(b1));
}
// fp32 -> (bf16 hi, bf16 lo residual)
__device__ __forceinline__ void split_bf(float x, __nv_bfloat16& h, __nv_bfloat16& l) {
    h = __float2bfloat16(x);
    l = __float2bfloat16(x - __bfloat162float(h));
}

// ---------------------------------------------------------------------------
// Prep: W_h[k][h] fp32 -> g_whT_{h,l}[n][k] bf16 split (padded stride 136).
// ---------------------------------------------------------------------------
__global__ __launch_bounds__(256) void k_prep(const float* __restrict__ Wh) {
    int i = blockIdx.x * 256 + threadIdx.x;  // 16384
    int n = i >> 7, k = i & 127;
    __nv_bfloat16 h, l;
    split_bf(Wh[k * H_N + n], h, l);
    g_whT_h[n * BST + k] = h;
    g_whT_l[n * BST + k] = l;
}

// One-time: tree_message fp32 -> bf16.
__global__ __launch_bounds__(256) void k_tree(const float* __restrict__ tree) {
    int i = blockIdx.x * 256 + threadIdx.x;
    float4 v = ((const float4*)tree)[i];
    ((uint2*)g_tr)[i] = to_bf4(v);
}

// ---------------------------------------------------------------------------
// fp32 scalar tile GEMM (k_binput / k_atom — unchanged from R9)
// ---------------------------------------------------------------------------
template <int K4B, int K4E, int XS4>
__device__ __forceinline__ void gemm_part(const float* sW, const float* sX,
                                          int wy, int tx, float4 acc[8]) {
    const float4* w4 = (const float4*)sW;
    const float4* x4 = (const float4*)sX;
#pragma unroll
    for (int k4 = K4B; k4 < K4E; k4++) {
        float4 wv[4];
#pragma unroll
        for (int kk = 0; kk < 4; kk++) wv[kk] = w4[(k4 * 4 + kk) * 32 + tx];
#pragma unroll
        for (int rr = 0; rr < 8; rr++) {
            float4 xv = x4[(wy + rr * 8) * XS4 + k4];
            acc[rr].x = fmaf(xv.x, wv[0].x, acc[rr].x);
            acc[rr].y = fmaf(xv.x, wv[0].y, acc[rr].y);
            acc[rr].z = fmaf(xv.x, wv[0].z, acc[rr].z);
            acc[rr].w = fmaf(xv.x, wv[0].w, acc[rr].w);
            acc[rr].x = fmaf(xv.y, wv[1].x, acc[rr].x);
            acc[rr].y = fmaf(xv.y, wv[1].y, acc[rr].y);
            acc[rr].z = fmaf(xv.y, wv[1].z, acc[rr].z);
            acc[rr].w = fmaf(xv.y, wv[1].w, acc[rr].w);
            acc[rr].x = fmaf(xv.z, wv[2].x, acc[rr].x);
            acc[rr].y = fmaf(xv.z, wv[2].y, acc[rr].y);
            acc[rr].z = fmaf(xv.z, wv[2].z, acc[rr].z);
            acc[rr].w = fmaf(xv.z, wv[2].w, acc[rr].w);
            acc[rr].x = fmaf(xv.w, wv[3].x, acc[rr].x);
            acc[rr].y = fmaf(xv.w, wv[3].y, acc[rr].y);
            acc[rr].z = fmaf(xv.w, wv[3].z, acc[rr].z);
            acc[rr].w = fmaf(xv.w, wv[3].w, acc[rr].w);
        }
    }
}

__global__ __launch_bounds__(256, 2) void k_binput(const float* __restrict__ fbonds,
                                                   const float* __restrict__ Wi) {
    __shared__ __align__(16) float sW[FB * H_N];
    __shared__ __align__(16) float sF[64 * FB];
    int t = threadIdx.x;
    int tx = t & 31, wy = t >> 5;
    int b0 = blockIdx.x * 64;
    {
        const float4* src = (const float4*)Wi;
        float4* dst = (float4*)sW;
#pragma unroll
        for (int i = t; i < FB * H_N / 4; i += 256) dst[i] = src[i];
    }
    {
        const float4* src = (const float4*)(fbonds + (size_t)b0 * FB);
        float4* dst = (float4*)sF;
#pragma unroll
        for (int i = t; i < 64 * FB / 4; i += 256) dst[i] = __ldcs(src + i);
    }
    __syncthreads();
    float4 acc[8];
#pragma unroll
    for (int r = 0; r < 8; r++) acc[r] = make_float4(0.f, 0.f, 0.f, 0.f);
    gemm_part<0, FB / 4, FB / 4>(sW, sF, wy, tx, acc);
#pragma unroll
    for (int rr = 0; rr < 8; rr++) {
        size_t b = (size_t)(b0 + wy + rr * 8);
        ((float4*)g_binput)[b * 32 + tx] = acc[rr];
        float4 o = make_float4(fmaxf(acc[rr].x, 0.f), fmaxf(acc[rr].y, 0.f),
                               fmaxf(acc[rr].z, 0.f), fmaxf(acc[rr].w, 0.f));
        ((uint2*)g_gm0)[b * 32 + tx] = to_bf4(o);
    }
}

// ---------------------------------------------------------------------------
// HMMA MP iteration with hi/lo error compensation:
//   A@W ≈ a_hi@w_hi + a_lo@w_hi + a_hi@w_lo  (fp32 accum, one accumulator)
// 128 bonds/block, 1 CTA/SM. smem: A_hi, A_lo, B_hi, B_lo (4 x 34816 B).
// ---------------------------------------------------------------------------
#define T_BY (128 * BST * 2)            // 34816 B per tile
#define MM_SMEM (4 * T_BY)              // 139264 B

__global__ __launch_bounds__(256, 1) void k_iter_mma(const int* __restrict__ bgraph,
                                                     int srcsel) {
    extern __shared__ char sm[];
    __nv_bfloat16* sAh = (__nv_bfloat16*)sm;
    __nv_bfloat16* sAl = (__nv_bfloat16*)(sm + T_BY);
    __nv_bfloat16* sBh = (__nv_bfloat16*)(sm + 2 * T_BY);
    __nv_bfloat16* sBl = (__nv_bfloat16*)(sm + 3 * T_BY);
    const __nv_bfloat16* src = srcsel ? g_gm1 : g_gm0;
    __nv_bfloat16* dst = srcsel ? g_gm0 : g_gm1;
    int t = threadIdx.x;
    int b0 = blockIdx.x * 128;

    // stage B hi+lo (2 x 2176 uint4)
    {
        const uint4* sh = (const uint4*)g_whT_h;
        const uint4* sl = (const uint4*)g_whT_l;
        uint4* dh = (uint4*)sBh;
        uint4* dl = (uint4*)sBl;
#pragma unroll
        for (int i = t; i < 2176; i += 256) { dh[i] = sh[i]; dl[i] = sl[i]; }
    }

    // gather: two halves of 64 rows; 4 threads/row, 32 cols each; fp32 accum
#pragma unroll
    for (int half = 0; half < 2; half++) {
        int row = half * 64 + (t >> 2);
        int q = t & 3;
        int bond = b0 + row;
        int bsafe = bond < B_N ? bond : B_N - 1;
        const int* gp = bgraph + (size_t)bsafe * MAXNB;
        const __nv_bfloat16* pb[MAXNB];
#pragma unroll
        for (int j = 0; j < MAXNB; j++) {
            int idx = gp[j];
            const __nv_bfloat16* p = (idx < M_N) ? (g_tr + (size_t)idx * H_N)
                                                 : (src + (size_t)(idx - M_N) * H_N);
            pb[j] = p + q * 32;
        }
        float acc[32];
#pragma unroll
        for (int i = 0; i < 32; i++) acc[i] = 0.f;
#pragma unroll
        for (int j = 0; j < MAXNB; j++) {
            const uint4* p4 = (const uint4*)pb[j];
#pragma unroll
            for (int c4 = 0; c4 < 4; c4++) {
                uint4 v = p4[c4];
                const unsigned* u = &v.x;
#pragma unroll
                for (int e = 0; e < 4; e++) {
                    float2 f = __bfloat1622float2(*(const __nv_bfloat162*)&u[e]);
                    acc[c4 * 8 + e * 2] += f.x;
                    acc[c4 * 8 + e * 2 + 1] += f.y;
                }
            }
        }
        int off = row * BST + q * 32;
#pragma unroll
        for (int c4 = 0; c4 < 4; c4++) {
            __nv_bfloat16 h[8], l[8];
#pragma unroll
            for (int e = 0; e < 8; e++) split_bf(acc[c4 * 8 + e], h[e], l[e]);
            uint4 oh, ol;
            oh.x = *(unsigned*)&h[0] | ((unsigned)*(unsigned short*)&h[1] << 16);
            // pack via bf2-style: reinterpret pairs
            oh.x = bf2(__bfloat162float(h[0]), __bfloat162float(h[1]));
            oh.y = bf2(__bfloat162float(h[2]), __bfloat162float(h[3]));
            oh.z = bf2(__bfloat162float(h[4]), __bfloat162float(h[5]));
            oh.w = bf2(__bfloat162float(h[6]), __bfloat162float(h[7]));
            ol.x = bf2(__bfloat162float(l[0]), __bfloat162float(l[1]));
            ol.y = bf2(__bfloat162float(l[2]), __bfloat162float(l[3]));
            ol.z = bf2(__bfloat162float(l[4]), __bfloat162float(l[5]));
            ol.w = bf2(__bfloat162float(l[6]), __bfloat162float(l[7]));
            ((uint4*)(sAh + off))[c4] = oh;
            ((uint4*)(sAl + off))[c4] = ol;
        }
    }
    __syncthreads();

    // mma phase: warp w -> rows w*16..+15, all 128 cols; 3-term compensation
    int w = t >> 5, lane = t & 31;
    int quad = lane >> 3, li = lane & 7;
    int mrow = w * 16;
    float c[16][4];
#pragma unroll
    for (int i = 0; i < 16; i++)
#pragma unroll
        for (int j = 0; j < 4; j++) c[i][j] = 0.f;
    uint32_t aHB = smem_u32(sAh), aLB = smem_u32(sAl);
    uint32_t bHB = smem_u32(sBh), bLB = smem_u32(sBl);
    uint32_t arow = (mrow + (quad & 1) * 8 + li) * (BST * 2);
    uint32_t brow0 = ((quad >> 1) * 8 + li) * (BST * 2);
#pragma unroll
    for (int ks = 0; ks < 8; ks++) {
        int k0 = ks * 16;
        uint32_t akoff = (k0 + (quad >> 1) * 8) * 2;
        uint32_t bkoff = (k0 + (quad & 1) * 8) * 2;
        uint32_t ah0, ah1, ah2, ah3, al0, al1, al2, al3;
        ldsm_x4(aHB + arow + akoff, ah0, ah1, ah2, ah3);
        ldsm_x4(aLB + arow + akoff, al0, al1, al2, al3);
#pragma unroll
        for (int np = 0; np < 8; np++) {
            uint32_t bro = brow0 + np * 16 * (BST * 2);
            uint32_t bh0, bh1, bh2, bh3, bl0, bl1, bl2, bl3;
            ldsm_x4(bHB + bro + bkoff, bh0, bh1, bh2, bh3);
            ldsm_x4(bLB + bro + bkoff, bl0, bl1, bl2, bl3);
            mma16816(c[np * 2], ah0, ah1, ah2, ah3, bh0, bh1);
            mma16816(c[np * 2], al0, al1, al2, al3, bh0, bh1);
            mma16816(c[np * 2], ah0, ah1, ah2, ah3, bl0, bl1);
            mma16816(c[np * 2 + 1], ah0, ah1, ah2, ah3, bh2, bh3);
            mma16816(c[np * 2 + 1], al0, al1, al2, al3, bh2, bh3);
            mma16816(c[np * 2 + 1], ah0, ah1, ah2, ah3, bl2, bl3);
        }
    }

    // epilogue: + fp32 binput, relu, bf16 store (c[nt] -> cols nt*8 + cc)
    int r0 = mrow + (lane >> 2);
    int cc = (lane & 3) * 2;
#pragma unroll
    for (int rr = 0; rr < 2; rr++) {
        int bond = b0 + r0 + rr * 8;
        if (bond < B_N) {
            const float2* bi = (const float2*)(g_binput + (size_t)bond * H_N + cc);
            unsigned* dp = (unsigned*)(dst + (size_t)bond * H_N + cc);
#pragma unroll
            for (int nt = 0; nt < 16; nt++) {
                float2 b = __ldcs(bi + nt * 4);           // element offset nt*8
                float x = fmaxf(c[nt][rr * 2 + 0] + b.x, 0.f);
                float y = fmaxf(c[nt][rr * 2 + 1] + b.y, 0.f);
                dp[nt * 4] = bf2(x, y);                   // element offset nt*8
            }
        }
    }
}

// ---------------------------------------------------------------------------
// Atom stage (R9 scalar): ah = relu([fatoms, gather] @ W_o + b_o)
// ---------------------------------------------------------------------------
__device__ __forceinline__ void gb_issue(const __nv_bfloat16* const* pb, int k0,
                                         uint4 v[4]) {
#pragma unroll
    for (int j = 0; j < 4; j++) v[j] = *(const uint4*)(pb[j] + k0);
}
__device__ __forceinline__ void gb_sum(const uint4 v[4], float4& s0, float4& s1) {
#pragma unroll
    for (int j = 0; j < 4; j++) {
        float2 f;
        f = __bfloat1622float2(*(const __nv_bfloat162*)&v[j].x); s0.x += f.x; s0.y += f.y;
        f = __bfloat1622float2(*(const __nv_bfloat162*)&v[j].y); s0.z += f.x; s0.w += f.y;
        f = __bfloat1622float2(*(const __nv_bfloat162*)&v[j].z); s1.x += f.x; s1.y += f.y;
        f = __bfloat1622float2(*(const __nv_bfloat162*)&v[j].w); s1.z += f.x; s1.w += f.y;
    }
}
__device__ __forceinline__ void g_ptrs(const int* __restrict__ gp,
                                       const __nv_bfloat16* __restrict__ src,
                                       int q, const __nv_bfloat16* pb[MAXNB]) {
#pragma unroll
    for (int j = 0; j < MAXNB; j++) {
        int idx = gp[j];
        const __nv_bfloat16* p = (idx < M_N) ? (g_tr + (size_t)idx * H_N)
                                             : (src + (size_t)(idx - M_N) * H_N);
        pb[j] = p + q * 8;
    }
}

__global__ __launch_bounds__(256, 2) void k_atom(const float* __restrict__ fatoms,
                                                  const int* __restrict__ agraph,
                                                  const float* __restrict__ Wo,
                                                  const float* __restrict__ bo) {
    __shared__ __align__(16) float sW[36 * H_N];
    __shared__ __align__(16) float sX[2][64 * 36];
    int t = threadIdx.x;
    int tx = t & 31, wy = t >> 5;
    int row = t >> 2, q = t & 3;
    int a0 = blockIdx.x * 64;
    bool rvalid = (a0 + row) < A_N;

    const __nv_bfloat16* pb[MAXNB];
    g_ptrs(agraph + (size_t)(rvalid ? (a0 + row) : 0) * MAXNB, g_gm0, q, pb);

    float4 bov = ((const float4*)bo)[tx];
    float4 acc[8];
#pragma unroll
    for (int r = 0; r < 8; r++) acc[r] = bov;

    {
        const float4* wsrc = (const float4*)Wo;
        float4* wdst = (float4*)sW;
        float4 z4 = make_float4(0.f, 0.f, 0.f, 0.f);
#pragma unroll
        for (int i = t; i < 36 * H_N / 4; i += 256)
            wdst[i] = (i < FA * H_N / 4) ? wsrc[i] : z4;
        for (int i = t; i < 64 * 36; i += 256) {
            int r = i / 36;
            int c = i - r * 36;
            int a = a0 + r;
            sX[0][r * 36 + c] = (c < FA && a < A_N) ? __ldcs(fatoms + (size_t)a * FA + c) : 0.f;
        }
    }
    __syncthreads();
    float4 s0 = {0.f, 0.f, 0.f, 0.f}, s1 = s0;
    {
        uint4 va[4];
        gb_issue(pb, 0, va);
        gemm_part<0, 5, 9>(sW, sX[0], wy, tx, acc);
        gb_sum(va, s0, s1);
        gb_issue(pb + 4, 0, va);
        gemm_part<5, 9, 9>(sW, sX[0], wy, tx, acc);
        gb_sum(va, s0, s1);
    }

#pragma unroll
    for (int c = 0; c < 4; c++) {
        int buf = (c + 1) & 1;
        {
            float4* o = (float4*)(sX[buf] + row * 32) + q * 2;
            o[0] = s0; o[1] = s1;
        }
        __syncthreads();
        {
            const float4* wsrc = (const float4*)(Wo + (size_t)(FA + c * 32) * H_N);
            float4* wdst = (float4*)sW;
#pragma unroll
            for (int i = 0; i < 4; i++) wdst[t + i * 256] = wsrc[t + i * 256];
        }
        __syncthreads();
        uint4 va[4];
        int k0n = (c + 1) * 32;
        if (c < 3) gb_issue(pb, k0n, va);
        gemm_part<0, 4, 8>(sW, sX[buf], wy, tx, acc);
        float4 t0 = {0.f, 0.f, 0.f, 0.f}, t1 = t0;
        if (c < 3) { gb_sum(va, t0, t1); gb_issue(pb + 4, k0n, va); }
        gemm_part<4, 8, 8>(sW, sX[buf], wy, tx, acc);
        if (c < 3) { gb_sum(va, t0, t1); s0 = t0; s1 = t1; }
    }
#pragma unroll
    for (int rr = 0; rr < 8; rr++) {
        int a = a0 + wy + rr * 8;
        if (a < A_N) {
            float4 o = make_float4(fmaxf(acc[rr].x, 0.f), fmaxf(acc[rr].y, 0.f),
                                   fmaxf(acc[rr].z, 0.f), fmaxf(acc[rr].w, 0.f));
            __stcs(((float4*)g_ah) + (size_t)a * 32 + tx, o);
        }
    }
}

// ---------------------------------------------------------------------------
__global__ __launch_bounds__(128) void k_mol(const int* __restrict__ mol_id,
                                             float* __restrict__ out) {
    int m = blockIdx.x;
    int h = threadIdx.x;
    __shared__ int sb2[2];
    if (h < 2) {
        int v = m + h;
        int lo = 0, hi = A_N;
        while (lo < hi) {
            int mid = (lo + hi) >> 1;
            if (mol_id[mid] < v) lo = mid + 1;
            else hi = mid;
        }
        sb2[h] = lo;
    }
    __syncthreads();
    int lo = sb2[0], hi = sb2[1];
    float s = 0.f;
    for (int a = lo; a < hi; a++) s += __ldcs(g_ah + (size_t)a * H_N + h);
    out[(size_t)m * H_N + h] = s / fmaxf((float)(hi - lo), 1.f);
}

// ---------------------------------------------------------------------------
extern "C" void kernel_launch(void* const* d_in, const int* in_sizes, int n_in,
                              void* d_out, int out_size) {
    const float* fatoms = (const float*)d_in[0];
    const float* fbonds = (const float*)d_in[1];
    const float* tree   = (const float*)d_in[2];
    const int*   agraph = (const int*)d_in[3];
    const int*   bgraph = (const int*)d_in[4];
    const int*   mol_id = (const int*)d_in[5];
    const float* Wi     = (const float*)d_in[6];
    const float* Wh     = (const float*)d_in[7];
    const float* Wo     = (const float*)d_in[8];
    const float* bo     = (const float*)d_in[9];
    float* out = (float*)d_out;

    cudaFuncSetAttribute(k_iter_mma, cudaFuncAttributeMaxDynamicSharedMemorySize, MM_SMEM);

    k_tree<<<M_N * H_N / 4 / 256, 256>>>(tree);
    k_prep<<<64, 256>>>(Wh);
    k_binput<<<B_N / 64, 256>>>(fbonds, Wi);
    int grid = (B_N + 127) / 128;
    k_iter_mma<<<grid, 256, MM_SMEM>>>(bgraph, 0);  // gm0 -> gm1
    k_iter_mma<<<grid, 256, MM_SMEM>>>(bgraph, 1);  // gm1 -> gm0
    k_iter_mma<<<grid, 256, MM_SMEM>>>(bgraph, 0);  // gm0 -> gm1
    k_iter_mma<<<grid, 256, MM_SMEM>>>(bgraph, 1);  // gm1 -> gm0 (final)
    k_atom<<<(A_N + 63) / 64, 256>>>(fatoms, agraph, Wo, bo);
    k_mol<<<NMOL_N, 128>>>(mol_id, out);
}